// round 9
// baseline (speedup 1.0000x reference)
#include <cuda_runtime.h>
#include <cuda_bf16.h>
#include <stdint.h>
#include <math.h>

// ---------------------------------------------------------------------------
// LN-LSTM cell.  B=4096, IN=1024, H=2048, OUT=1024.
// GEMMs via mma.sync bf16 (HMMA) with hi/lo split: A_cat=[hi|lo|hi],
// W_cat=[hi|hi|lo] along K (3K), fp32 accumulation.
// ---------------------------------------------------------------------------

#define BDIM 4096
#define HDIM 2048
#define EPS_LN 1e-5f

__device__ float g_Xbuf[(size_t)BDIM * 4 * HDIM];
__device__ float g_Hbuf[(size_t)BDIM * 4 * HDIM];
__device__ __nv_bfloat16 g_Ax[(size_t)BDIM * 3 * 1024];
__device__ __nv_bfloat16 g_Ah[(size_t)BDIM * 3 * HDIM];
__device__ __nv_bfloat16 g_Wx[(size_t)4 * HDIM * 3 * 1024];
__device__ __nv_bfloat16 g_Wh[(size_t)4 * HDIM * 3 * HDIM];
__device__ __nv_bfloat16 g_Wd[(size_t)1024 * 3 * HDIM];
__device__ __nv_bfloat16 g_Hxc[(size_t)BDIM * 3 * HDIM];
__device__ float g_biasx[4 * HDIM];
__device__ float g_biash[4 * HDIM];

// ------------------------------- helpers -----------------------------------
__device__ __forceinline__ uint32_t smem_u32(const void* p) {
    uint32_t a;
    asm("{ .reg .u64 t; cvta.to.shared.u64 t, %1; cvt.u32.u64 %0, t; }" : "=r"(a) : "l"(p));
    return a;
}
#define CP_ASYNC16(dst, src) \
    asm volatile("cp.async.cg.shared.global [%0], [%1], 16;" :: "r"(dst), "l"(src) : "memory")
#define CP_COMMIT()  asm volatile("cp.async.commit_group;" ::: "memory")
#define CP_WAIT1()   asm volatile("cp.async.wait_group 1;" ::: "memory")

// ---------------------------------------------------------------------------
// HMMA GEMM: C[M,Ntot] = Acat[M,Kcat] * Wcat[Ntot,Kcat]^T + bias
// CTA 128x256, BK=64, 3-stage cp.async, 8 warps of 64x64, m16n8k16 bf16.
// ---------------------------------------------------------------------------
#define BM 128
#define BN 256
#define BK 64
#define NSTG 3
#define STG_BYTES 49152                 // A(16KB) + B(32KB)
#define GEMM_SMEM (NSTG * STG_BYTES)    // 147456

__global__ void __launch_bounds__(256, 1) gemm_mma(
    const __nv_bfloat16* __restrict__ A, const __nv_bfloat16* __restrict__ W,
    const float* __restrict__ bias, float* __restrict__ C, int Kcat, int Ntot)
{
    extern __shared__ char smem[];
    const uint32_t sb = smem_u32(smem);
    const int tid  = threadIdx.x;
    const int lane = tid & 31, wid = tid >> 5;
    const int wm = wid & 1, wn = wid >> 1;            // warp grid 2 x 4 (64x64 tiles)
    const int m0 = blockIdx.x * BM, n0 = blockIdx.y * BN;
    const int nkt = Kcat / BK;

    // cp.async mapping: A: 128 rows x 8 chunks, thread -> (row=tid>>1, half=tid&1), 4 chunks
    //                   B: 256 rows x 8 chunks, thread -> row=tid, 8 chunks
    const int arow  = tid >> 1;
    const int ahalf = tid & 1;
    const __nv_bfloat16* agp = A + (size_t)(m0 + arow) * Kcat + ahalf * 32;
    const __nv_bfloat16* bgp = W + (size_t)(n0 + tid) * Kcat;

#define LOADT(kt, stg) do {                                                     \
    const __nv_bfloat16* a_ = agp + (size_t)(kt) * BK;                          \
    const __nv_bfloat16* b_ = bgp + (size_t)(kt) * BK;                          \
    const uint32_t as_ = sb + (stg) * STG_BYTES;                                \
    const uint32_t bs_ = as_ + 16384;                                           \
    _Pragma("unroll")                                                           \
    for (int j = 0; j < 4; j++) {                                               \
        const uint32_t g   = ahalf * 4 + j;                                     \
        const uint32_t off = arow * 128 + ((g ^ (arow & 7)) << 4);              \
        CP_ASYNC16(as_ + off, a_ + j * 8);                                      \
    }                                                                           \
    _Pragma("unroll")                                                           \
    for (int g = 0; g < 8; g++) {                                               \
        const uint32_t off = tid * 128 + (((uint32_t)g ^ (tid & 7)) << 4);      \
        CP_ASYNC16(bs_ + off, b_ + g * 8);                                      \
    }                                                                           \
} while (0)

    // ldmatrix addressing
    const int a_r16 = lane & 15;
    const int a_h   = lane >> 4;
    const int b_sel = lane >> 3, b_tr = lane & 7;
    const int b_roff = ((b_sel >> 1) & 1) * 8 + b_tr;
    const int b_h    = b_sel & 1;

    float acc[4][8][4];
    #pragma unroll
    for (int i = 0; i < 4; i++)
        #pragma unroll
        for (int j = 0; j < 8; j++)
            #pragma unroll
            for (int q = 0; q < 4; q++) acc[i][j][q] = 0.0f;

    LOADT(0, 0); CP_COMMIT();
    LOADT(1, 1); CP_COMMIT();

    for (int kt = 0; kt < nkt; kt++) {
        const int stg = kt % NSTG;
        CP_WAIT1();
        __syncthreads();
        const uint32_t as_ = sb + stg * STG_BYTES;
        const uint32_t bs_ = as_ + 16384;

        #pragma unroll
        for (int kk = 0; kk < 4; kk++) {
            uint32_t a[4][4], b[4][4];
            #pragma unroll
            for (int mf = 0; mf < 4; mf++) {
                const int r = wm * 64 + mf * 16 + a_r16;
                const uint32_t ad = as_ + r * 128 + (((kk * 2 + a_h) ^ (r & 7)) << 4);
                asm volatile("ldmatrix.sync.aligned.m8n8.x4.shared.b16 {%0,%1,%2,%3}, [%4];"
                    : "=r"(a[mf][0]), "=r"(a[mf][1]), "=r"(a[mf][2]), "=r"(a[mf][3])
                    : "r"(ad));
            }
            #pragma unroll
            for (int p = 0; p < 4; p++) {
                const int r = wn * 64 + p * 16 + b_roff;
                const uint32_t bd = bs_ + r * 128 + (((kk * 2 + b_h) ^ (r & 7)) << 4);
                asm volatile("ldmatrix.sync.aligned.m8n8.x4.shared.b16 {%0,%1,%2,%3}, [%4];"
                    : "=r"(b[p][0]), "=r"(b[p][1]), "=r"(b[p][2]), "=r"(b[p][3])
                    : "r"(bd));
            }
            #pragma unroll
            for (int mf = 0; mf < 4; mf++)
                #pragma unroll
                for (int nf = 0; nf < 8; nf++) {
                    const uint32_t b0 = b[nf >> 1][(nf & 1) * 2 + 0];
                    const uint32_t b1 = b[nf >> 1][(nf & 1) * 2 + 1];
                    asm volatile(
                        "mma.sync.aligned.m16n8k16.row.col.f32.bf16.bf16.f32 "
                        "{%0,%1,%2,%3}, {%4,%5,%6,%7}, {%8,%9}, {%0,%1,%2,%3};"
                        : "+f"(acc[mf][nf][0]), "+f"(acc[mf][nf][1]),
                          "+f"(acc[mf][nf][2]), "+f"(acc[mf][nf][3])
                        : "r"(a[mf][0]), "r"(a[mf][1]), "r"(a[mf][2]), "r"(a[mf][3]),
                          "r"(b0), "r"(b1));
                }
        }
        if (kt + NSTG - 1 < nkt) LOADT(kt + NSTG - 1, (kt + NSTG - 1) % NSTG);
        CP_COMMIT();
    }

    // epilogue: bias + store
    const int er = lane >> 2, ec = (lane & 3) * 2;
    #pragma unroll
    for (int mf = 0; mf < 4; mf++) {
        const int grow = m0 + wm * 64 + mf * 16 + er;
        #pragma unroll
        for (int nf = 0; nf < 8; nf++) {
            const int gcol = n0 + wn * 64 + nf * 8 + ec;
            const float bx0 = __ldg(bias + gcol), bx1 = __ldg(bias + gcol + 1);
            float2 v0 = make_float2(acc[mf][nf][0] + bx0, acc[mf][nf][1] + bx1);
            float2 v1 = make_float2(acc[mf][nf][2] + bx0, acc[mf][nf][3] + bx1);
            *(float2*)&C[(size_t)grow * Ntot + gcol] = v0;
            *(float2*)&C[(size_t)(grow + 8) * Ntot + gcol] = v1;
        }
    }
}

// ---------------------------------------------------------------------------
// split fp32 -> bf16 hi/lo cat.  mode 0 (activations): [hi | lo | hi]
// ---------------------------------------------------------------------------
__global__ void __launch_bounds__(256) split_kernel(
    const float* __restrict__ in, __nv_bfloat16* __restrict__ out, int K, int mode)
{
    const int row = blockIdx.x;
    const float* src = in + (size_t)row * K;
    __nv_bfloat16* d = out + (size_t)row * 3 * K;
    for (int c = threadIdx.x; c < K; c += 256) {
        const float x = src[c];
        const __nv_bfloat16 hi = __float2bfloat16(x);
        const __nv_bfloat16 lo = __float2bfloat16(x - __bfloat162float(hi));
        if (mode == 0) { d[c] = hi; d[K + c] = lo; d[2 * K + c] = hi; }
        else           { d[c] = hi; d[K + c] = hi; d[2 * K + c] = lo; }
    }
}

// 4 weight matrices (one per gate), mode 1 cat: [hi | hi | lo]
__global__ void __launch_bounds__(256) splitW4_kernel(
    const float* __restrict__ w0, const float* __restrict__ w1,
    const float* __restrict__ w2, const float* __restrict__ w3,
    __nv_bfloat16* __restrict__ out, int K)
{
    const int row = blockIdx.x, gate = blockIdx.y;
    const float* w = (gate == 0) ? w0 : (gate == 1) ? w1 : (gate == 2) ? w2 : w3;
    const float* src = w + (size_t)row * K;
    __nv_bfloat16* d = out + ((size_t)gate * gridDim.x + row) * 3 * K;
    for (int c = threadIdx.x; c < K; c += 256) {
        const float x = src[c];
        const __nv_bfloat16 hi = __float2bfloat16(x);
        const __nv_bfloat16 lo = __float2bfloat16(x - __bfloat162float(hi));
        d[c] = hi; d[K + c] = hi; d[2 * K + c] = lo;
    }
}

__global__ void __launch_bounds__(256) bias4_kernel(
    const float* __restrict__ b0, const float* __restrict__ b1,
    const float* __restrict__ b2, const float* __restrict__ b3, float* __restrict__ out)
{
    const int i = blockIdx.x * 256 + threadIdx.x;
    const int g = i >> 11, c = i & 2047;
    out[i] = (g == 0) ? b0[c] : (g == 1) ? b1[c] : (g == 2) ? b2[c] : b3[c];
}

// ---------------------------------------------------------------------------
// Fused LN-combine + cell.  One block per batch row, 512 threads x 4 cols.
//   per gate g: G_g = LN(X_g;ax,bx) + LN(H_g;ah,bh)
//   cx = sig(Gf)*c0 + sig(Gi)*tanh(Gc);  hx = sig(Go)*tanh(LN(cx;ac,bc))
// Emits hx, cx and hx split-cat bf16 for the decoder GEMM.
// ---------------------------------------------------------------------------
__global__ void __launch_bounds__(512) ln_cell_kernel(
    const float* __restrict__ Xbuf, const float* __restrict__ Hbuf,
    const float* __restrict__ c0,
    const float* __restrict__ ax, const float* __restrict__ bxv,
    const float* __restrict__ ah, const float* __restrict__ bhv,
    const float* __restrict__ ac, const float* __restrict__ bcv,
    float* __restrict__ hx_out, float* __restrict__ cx_out,
    __nv_bfloat16* __restrict__ hxcat)
{
    const int row = blockIdx.x, tid = threadIdx.x;
    const int lane = tid & 31, wid = tid >> 5;
    const size_t base = (size_t)row * (4 * HDIM);

    float xv[4][4], hv[4][4];
    float p[16];
    #pragma unroll
    for (int v = 0; v < 16; v++) p[v] = 0.f;

    #pragma unroll
    for (int g = 0; g < 4; g++)
        #pragma unroll
        for (int i = 0; i < 4; i++) {
            const int c = tid + i * 512;
            const float x = Xbuf[base + g * HDIM + c];
            const float h = Hbuf[base + g * HDIM + c];
            xv[g][i] = x; hv[g][i] = h;
            p[g * 2 + 0] += x; p[g * 2 + 1] += x * x;
            p[8 + g * 2 + 0] += h; p[8 + g * 2 + 1] += h * h;
        }

    __shared__ float sm[16][16];
    __shared__ float smf[18];
    #pragma unroll
    for (int v = 0; v < 16; v++)
        #pragma unroll
        for (int o = 16; o > 0; o >>= 1)
            p[v] += __shfl_down_sync(0xffffffffu, p[v], o);
    if (lane == 0)
        #pragma unroll
        for (int v = 0; v < 16; v++) sm[wid][v] = p[v];
    __syncthreads();
    if (wid == 0 && lane < 16) {
        float s = 0.f;
        #pragma unroll
        for (int w = 0; w < 16; w++) s += sm[w][lane];
        smf[lane] = s;
    }
    __syncthreads();

    const float n = (float)HDIM;
    float mux[4], rx[4], muh[4], rh[4];
    #pragma unroll
    for (int g = 0; g < 4; g++) {
        const float sx = smf[g * 2], sxx = smf[g * 2 + 1];
        const float sh = smf[8 + g * 2], shh = smf[8 + g * 2 + 1];
        mux[g] = sx / n;
        muh[g] = sh / n;
        const float vx = (sxx - n * mux[g] * mux[g]) / (n - 1.0f);
        const float vh = (shh - n * muh[g] * muh[g]) / (n - 1.0f);
        rx[g] = 1.0f / (sqrtf(fmaxf(vx, 0.f)) + EPS_LN);
        rh[g] = 1.0f / (sqrtf(fmaxf(vh, 0.f)) + EPS_LN);
    }

    float cv[4], og[4];
    float s = 0.f, ss = 0.f;
    #pragma unroll
    for (int i = 0; i < 4; i++) {
        const int c = tid + i * 512;
        const float axc = ax[c], bxc = bxv[c], ahc = ah[c], bhc = bhv[c];
        float G[4];
        #pragma unroll
        for (int g = 0; g < 4; g++)
            G[g] = (xv[g][i] - mux[g]) * rx[g] * axc + bxc
                 + (hv[g][i] - muh[g]) * rh[g] * ahc + bhc;
        const float fg = 1.0f / (1.0f + expf(-G[0]));
        const float ig = 1.0f / (1.0f + expf(-G[1]));
        const float v  = fg * c0[(size_t)row * HDIM + c] + ig * tanhf(G[2]);
        cv[i] = v; og[i] = G[3];
        s += v; ss += v * v;
    }

    // second reduction: (s, ss)
    #pragma unroll
    for (int o = 16; o > 0; o >>= 1) {
        s  += __shfl_down_sync(0xffffffffu, s, o);
        ss += __shfl_down_sync(0xffffffffu, ss, o);
    }
    __syncthreads();
    if (lane == 0) { sm[wid][0] = s; sm[wid][1] = ss; }
    __syncthreads();
    if (wid == 0 && lane < 2) {
        float t = 0.f;
        #pragma unroll
        for (int w = 0; w < 16; w++) t += sm[w][lane];
        smf[16 + lane] = t;
    }
    __syncthreads();

    const float mu = smf[16] / n;
    const float var = (smf[17] - n * mu * mu) / (n - 1.0f);
    const float rs = 1.0f / (sqrtf(fmaxf(var, 0.f)) + EPS_LN);

    __nv_bfloat16* hrow = hxcat + (size_t)row * (3 * HDIM);
    #pragma unroll
    for (int i = 0; i < 4; i++) {
        const int c = tid + i * 512;
        const float lnc = (cv[i] - mu) * rs * ac[c] + bcv[c];
        const float o = 1.0f / (1.0f + expf(-og[i]));
        const float hvv = o * tanhf(lnc);
        hx_out[(size_t)row * HDIM + c] = hvv;
        cx_out[(size_t)row * HDIM + c] = cv[i];
        const __nv_bfloat16 hi = __float2bfloat16(hvv);
        const __nv_bfloat16 lo = __float2bfloat16(hvv - __bfloat162float(hi));
        hrow[c] = hi; hrow[HDIM + c] = lo; hrow[2 * HDIM + c] = hi;
    }
}

// ---------------------------------------------------------------------------
extern "C" void kernel_launch(void* const* d_in, const int* in_sizes, int n_in,
                              void* d_out, int out_size)
{
    (void)in_sizes; (void)n_in; (void)out_size;
    const float* inp = (const float*)d_in[0];
    const float* h0  = (const float*)d_in[1];
    const float* c0  = (const float*)d_in[2];
    const float* Wfh = (const float*)d_in[3];   const float* bfh = (const float*)d_in[4];
    const float* Wih = (const float*)d_in[5];   const float* bih = (const float*)d_in[6];
    const float* Wch = (const float*)d_in[7];   const float* bch = (const float*)d_in[8];
    const float* Woh = (const float*)d_in[9];   const float* boh = (const float*)d_in[10];
    const float* Wfx = (const float*)d_in[11];  const float* bfx = (const float*)d_in[12];
    const float* Wix = (const float*)d_in[13];  const float* bix = (const float*)d_in[14];
    const float* Wcx = (const float*)d_in[15];  const float* bcx = (const float*)d_in[16];
    const float* Wox = (const float*)d_in[17];  const float* box_ = (const float*)d_in[18];
    const float* Wdec = (const float*)d_in[19]; const float* bdec = (const float*)d_in[20];
    const float* ax = (const float*)d_in[21];   const float* bx = (const float*)d_in[22];
    const float* ah = (const float*)d_in[23];   const float* bh = (const float*)d_in[24];
    const float* ac = (const float*)d_in[25];   const float* bc = (const float*)d_in[26];

    float *Xbuf, *Hbuf, *biasx, *biash;
    __nv_bfloat16 *Ax, *Ah, *Wx, *Wh, *Wd, *Hxc;
    cudaGetSymbolAddress((void**)&Xbuf, g_Xbuf);
    cudaGetSymbolAddress((void**)&Hbuf, g_Hbuf);
    cudaGetSymbolAddress((void**)&Ax, g_Ax);
    cudaGetSymbolAddress((void**)&Ah, g_Ah);
    cudaGetSymbolAddress((void**)&Wx, g_Wx);
    cudaGetSymbolAddress((void**)&Wh, g_Wh);
    cudaGetSymbolAddress((void**)&Wd, g_Wd);
    cudaGetSymbolAddress((void**)&Hxc, g_Hxc);
    cudaGetSymbolAddress((void**)&biasx, g_biasx);
    cudaGetSymbolAddress((void**)&biash, g_biash);

    cudaFuncSetAttribute(gemm_mma, cudaFuncAttributeMaxDynamicSharedMemorySize, GEMM_SMEM);

    float* out = (float*)d_out;
    float* hx  = out + (size_t)BDIM * 1024;
    float* cx  = hx + (size_t)BDIM * HDIM;

    // launch order chosen so launch index 5 (ncu -s 5 -c 1) is the x-side GEMM
    split_kernel<<<BDIM, 256>>>(inp, Ax, 1024, 0);                         // 0
    splitW4_kernel<<<dim3(HDIM, 4), 256>>>(Wfx, Wix, Wcx, Wox, Wx, 1024);  // 1
    bias4_kernel<<<32, 256>>>(bfx, bix, bcx, box_, biasx);                 // 2
    split_kernel<<<BDIM, 256>>>(h0,  Ah, HDIM, 0);                         // 3
    splitW4_kernel<<<dim3(HDIM, 4), 256>>>(Wfh, Wih, Wch, Woh, Wh, HDIM);  // 4
    gemm_mma<<<dim3(BDIM / BM, (4 * HDIM) / BN), 256, GEMM_SMEM>>>(        // 5 <- profiled
        Ax, Wx, biasx, Xbuf, 3 * 1024, 4 * HDIM);
    bias4_kernel<<<32, 256>>>(bfh, bih, bch, boh, biash);                  // 6
    gemm_mma<<<dim3(BDIM / BM, (4 * HDIM) / BN), 256, GEMM_SMEM>>>(        // 7
        Ah, Wh, biash, Hbuf, 3 * HDIM, 4 * HDIM);
    split_kernel<<<1024, 256>>>(Wdec, Wd, HDIM, 1);                        // 8
    ln_cell_kernel<<<BDIM, 512>>>(Xbuf, Hbuf, c0, ax, bx, ah, bh, ac, bc,  // 9
                                  hx, cx, Hxc);
    gemm_mma<<<dim3(BDIM / BM, 1024 / BN), 256, GEMM_SMEM>>>(              // 10
        Hxc, Wd, bdec, out, 3 * HDIM, 1024);
}

// round 10
// speedup vs baseline: 1.2085x; 1.2085x over previous
#include <cuda_runtime.h>
#include <cuda_bf16.h>
#include <stdint.h>
#include <math.h>

// ---------------------------------------------------------------------------
// LN-LSTM cell.  B=4096, IN=1024, H=2048, OUT=1024.
// GEMMs via mma.sync bf16 (HMMA) with hi/lo split: A_cat=[hi|lo|hi],
// W_cat=[hi|hi|lo] along K (3K), fp32 accumulation.
// GEMM tile: 128x128x64, 3-stage cp.async, 2 CTA/SM (proven R5 config).
// ---------------------------------------------------------------------------

#define BDIM 4096
#define HDIM 2048
#define EPS_LN 1e-5f

__device__ float g_Xbuf[(size_t)BDIM * 4 * HDIM];
__device__ float g_Hbuf[(size_t)BDIM * 4 * HDIM];
__device__ __nv_bfloat16 g_Ax[(size_t)BDIM * 3 * 1024];
__device__ __nv_bfloat16 g_Ah[(size_t)BDIM * 3 * HDIM];
__device__ __nv_bfloat16 g_Wx[(size_t)4 * HDIM * 3 * 1024];
__device__ __nv_bfloat16 g_Wh[(size_t)4 * HDIM * 3 * HDIM];
__device__ __nv_bfloat16 g_Wd[(size_t)1024 * 3 * HDIM];
__device__ __nv_bfloat16 g_Hxc[(size_t)BDIM * 3 * HDIM];
__device__ float g_biasx[4 * HDIM];
__device__ float g_biash[4 * HDIM];

// ------------------------------- helpers -----------------------------------
__device__ __forceinline__ uint32_t smem_u32(const void* p) {
    uint32_t a;
    asm("{ .reg .u64 t; cvta.to.shared.u64 t, %1; cvt.u32.u64 %0, t; }" : "=r"(a) : "l"(p));
    return a;
}
#define CP_ASYNC16(dst, src) \
    asm volatile("cp.async.cg.shared.global [%0], [%1], 16;" :: "r"(dst), "l"(src) : "memory")
#define CP_COMMIT()  asm volatile("cp.async.commit_group;" ::: "memory")
#define CP_WAIT1()   asm volatile("cp.async.wait_group 1;" ::: "memory")

// ---------------------------------------------------------------------------
// HMMA GEMM:  C[M,Ntot] = Acat[M,Kcat] * Wcat[Ntot,Kcat]^T + bias
// CTA 128x128, BK=64, 3-stage cp.async, 8 warps of 64x32, m16n8k16 bf16.
// ---------------------------------------------------------------------------
#define BM 128
#define BN 128
#define BK 64
#define NSTG 3
#define STG_BYTES 32768                 // A(16KB) + B(16KB)
#define GEMM_SMEM (NSTG * STG_BYTES)    // 98304

__global__ void __launch_bounds__(256, 2) gemm_mma(
    const __nv_bfloat16* __restrict__ A, const __nv_bfloat16* __restrict__ W,
    const float* __restrict__ bias, float* __restrict__ C, int Kcat, int Ntot)
{
    extern __shared__ char smem[];
    const uint32_t sb = smem_u32(smem);
    const int tid  = threadIdx.x;
    const int lane = tid & 31, wid = tid >> 5;
    const int wm = wid & 1, wn = wid >> 1;            // warp grid 2 x 4
    const int m0 = blockIdx.x * BM, n0 = blockIdx.y * BN;
    const int nkt = Kcat / BK;

    const int lrow  = tid >> 1;
    const int lhalf = tid & 1;
    const __nv_bfloat16* agp = A + (size_t)(m0 + lrow) * Kcat + lhalf * 32;
    const __nv_bfloat16* bgp = W + (size_t)(n0 + lrow) * Kcat + lhalf * 32;

#define LOADT(kt, stg) do {                                                     \
    const __nv_bfloat16* a_ = agp + (size_t)(kt) * BK;                          \
    const __nv_bfloat16* b_ = bgp + (size_t)(kt) * BK;                          \
    const uint32_t as_ = sb + (stg) * STG_BYTES;                                \
    const uint32_t bs_ = as_ + 16384;                                           \
    _Pragma("unroll")                                                           \
    for (int j = 0; j < 4; j++) {                                               \
        const uint32_t g   = lhalf * 4 + j;                                     \
        const uint32_t off = lrow * 128 + ((g ^ (lrow & 7)) << 4);              \
        CP_ASYNC16(as_ + off, a_ + j * 8);                                      \
        CP_ASYNC16(bs_ + off, b_ + j * 8);                                      \
    }                                                                           \
} while (0)

    // ldmatrix addressing
    const int a_r16 = lane & 15;
    const int a_h   = lane >> 4;
    const int b_sel = lane >> 3, b_tr = lane & 7;
    const int b_roff = ((b_sel >> 1) & 1) * 8 + b_tr;
    const int b_h    = b_sel & 1;

    float acc[4][4][4];
    #pragma unroll
    for (int i = 0; i < 4; i++)
        #pragma unroll
        for (int j = 0; j < 4; j++)
            #pragma unroll
            for (int q = 0; q < 4; q++) acc[i][j][q] = 0.0f;

    LOADT(0, 0); CP_COMMIT();
    LOADT(1, 1); CP_COMMIT();

    for (int kt = 0; kt < nkt; kt++) {
        const int stg = kt % NSTG;
        CP_WAIT1();
        __syncthreads();
        const uint32_t as_ = sb + stg * STG_BYTES;
        const uint32_t bs_ = as_ + 16384;

        #pragma unroll
        for (int kk = 0; kk < 4; kk++) {
            uint32_t a[4][4], b[2][4];
            #pragma unroll
            for (int mf = 0; mf < 4; mf++) {
                const int r = wm * 64 + mf * 16 + a_r16;
                const uint32_t ad = as_ + r * 128 + (((kk * 2 + a_h) ^ (r & 7)) << 4);
                asm volatile("ldmatrix.sync.aligned.m8n8.x4.shared.b16 {%0,%1,%2,%3}, [%4];"
                    : "=r"(a[mf][0]), "=r"(a[mf][1]), "=r"(a[mf][2]), "=r"(a[mf][3])
                    : "r"(ad));
            }
            #pragma unroll
            for (int p = 0; p < 2; p++) {
                const int r = wn * 32 + p * 16 + b_roff;
                const uint32_t bd = bs_ + r * 128 + (((kk * 2 + b_h) ^ (r & 7)) << 4);
                asm volatile("ldmatrix.sync.aligned.m8n8.x4.shared.b16 {%0,%1,%2,%3}, [%4];"
                    : "=r"(b[p][0]), "=r"(b[p][1]), "=r"(b[p][2]), "=r"(b[p][3])
                    : "r"(bd));
            }
            #pragma unroll
            for (int mf = 0; mf < 4; mf++)
                #pragma unroll
                for (int nf = 0; nf < 4; nf++) {
                    const uint32_t b0 = b[nf >> 1][(nf & 1) * 2 + 0];
                    const uint32_t b1 = b[nf >> 1][(nf & 1) * 2 + 1];
                    asm volatile(
                        "mma.sync.aligned.m16n8k16.row.col.f32.bf16.bf16.f32 "
                        "{%0,%1,%2,%3}, {%4,%5,%6,%7}, {%8,%9}, {%0,%1,%2,%3};"
                        : "+f"(acc[mf][nf][0]), "+f"(acc[mf][nf][1]),
                          "+f"(acc[mf][nf][2]), "+f"(acc[mf][nf][3])
                        : "r"(a[mf][0]), "r"(a[mf][1]), "r"(a[mf][2]), "r"(a[mf][3]),
                          "r"(b0), "r"(b1));
                }
        }
        if (kt + NSTG - 1 < nkt) LOADT(kt + NSTG - 1, (kt + NSTG - 1) % NSTG);
        CP_COMMIT();
    }

    // epilogue: bias + store
    const int er = lane >> 2, ec = (lane & 3) * 2;
    #pragma unroll
    for (int mf = 0; mf < 4; mf++) {
        const int grow = m0 + wm * 64 + mf * 16 + er;
        #pragma unroll
        for (int nf = 0; nf < 4; nf++) {
            const int gcol = n0 + wn * 32 + nf * 8 + ec;
            const float bx0 = __ldg(bias + gcol), bx1 = __ldg(bias + gcol + 1);
            float2 v0 = make_float2(acc[mf][nf][0] + bx0, acc[mf][nf][1] + bx1);
            float2 v1 = make_float2(acc[mf][nf][2] + bx0, acc[mf][nf][3] + bx1);
            *(float2*)&C[(size_t)grow * Ntot + gcol] = v0;
            *(float2*)&C[(size_t)(grow + 8) * Ntot + gcol] = v1;
        }
    }
}

// ---------------------------------------------------------------------------
// split fp32 -> bf16 hi/lo cat.  mode 0 (activations): [hi | lo | hi]
// ---------------------------------------------------------------------------
__global__ void __launch_bounds__(256) split_kernel(
    const float* __restrict__ in, __nv_bfloat16* __restrict__ out, int K, int mode)
{
    const int row = blockIdx.x;
    const float* src = in + (size_t)row * K;
    __nv_bfloat16* d = out + (size_t)row * 3 * K;
    for (int c = threadIdx.x; c < K; c += 256) {
        const float x = src[c];
        const __nv_bfloat16 hi = __float2bfloat16(x);
        const __nv_bfloat16 lo = __float2bfloat16(x - __bfloat162float(hi));
        if (mode == 0) { d[c] = hi; d[K + c] = lo; d[2 * K + c] = hi; }
        else           { d[c] = hi; d[K + c] = hi; d[2 * K + c] = lo; }
    }
}

// 4 weight matrices (one per gate), mode 1 cat: [hi | hi | lo]
__global__ void __launch_bounds__(256) splitW4_kernel(
    const float* __restrict__ w0, const float* __restrict__ w1,
    const float* __restrict__ w2, const float* __restrict__ w3,
    __nv_bfloat16* __restrict__ out, int K)
{
    const int row = blockIdx.x, gate = blockIdx.y;
    const float* w = (gate == 0) ? w0 : (gate == 1) ? w1 : (gate == 2) ? w2 : w3;
    const float* src = w + (size_t)row * K;
    __nv_bfloat16* d = out + ((size_t)gate * gridDim.x + row) * 3 * K;
    for (int c = threadIdx.x; c < K; c += 256) {
        const float x = src[c];
        const __nv_bfloat16 hi = __float2bfloat16(x);
        const __nv_bfloat16 lo = __float2bfloat16(x - __bfloat162float(hi));
        d[c] = hi; d[K + c] = hi; d[2 * K + c] = lo;
    }
}

__global__ void __launch_bounds__(256) bias4_kernel(
    const float* __restrict__ b0, const float* __restrict__ b1,
    const float* __restrict__ b2, const float* __restrict__ b3, float* __restrict__ out)
{
    const int i = blockIdx.x * 256 + threadIdx.x;
    const int g = i >> 11, c = i & 2047;
    out[i] = (g == 0) ? b0[c] : (g == 1) ? b1[c] : (g == 2) ? b2[c] : b3[c];
}

// ---------------------------------------------------------------------------
// Fused LN-combine + cell.  One block per batch row, 512 threads x 4 cols.
//   per gate g: G_g = LN(X_g;ax,bx) + LN(H_g;ah,bh)
//   cx = sig(Gf)*c0 + sig(Gi)*tanh(Gc);  hx = sig(Go)*tanh(LN(cx;ac,bc))
// Emits hx, cx and hx split-cat bf16 for the decoder GEMM.
// ---------------------------------------------------------------------------
__global__ void __launch_bounds__(512) ln_cell_kernel(
    const float* __restrict__ Xbuf, const float* __restrict__ Hbuf,
    const float* __restrict__ c0,
    const float* __restrict__ ax, const float* __restrict__ bxv,
    const float* __restrict__ ah, const float* __restrict__ bhv,
    const float* __restrict__ ac, const float* __restrict__ bcv,
    float* __restrict__ hx_out, float* __restrict__ cx_out,
    __nv_bfloat16* __restrict__ hxcat)
{
    const int row = blockIdx.x, tid = threadIdx.x;
    const int lane = tid & 31, wid = tid >> 5;
    const size_t base = (size_t)row * (4 * HDIM);

    float xv[4][4], hv[4][4];
    float p[16];
    #pragma unroll
    for (int v = 0; v < 16; v++) p[v] = 0.f;

    #pragma unroll
    for (int g = 0; g < 4; g++)
        #pragma unroll
        for (int i = 0; i < 4; i++) {
            const int c = tid + i * 512;
            const float x = Xbuf[base + g * HDIM + c];
            const float h = Hbuf[base + g * HDIM + c];
            xv[g][i] = x; hv[g][i] = h;
            p[g * 2 + 0] += x; p[g * 2 + 1] += x * x;
            p[8 + g * 2 + 0] += h; p[8 + g * 2 + 1] += h * h;
        }

    __shared__ float sm[16][16];
    __shared__ float smf[18];
    #pragma unroll
    for (int v = 0; v < 16; v++)
        #pragma unroll
        for (int o = 16; o > 0; o >>= 1)
            p[v] += __shfl_down_sync(0xffffffffu, p[v], o);
    if (lane == 0)
        #pragma unroll
        for (int v = 0; v < 16; v++) sm[wid][v] = p[v];
    __syncthreads();
    if (wid == 0 && lane < 16) {
        float s = 0.f;
        #pragma unroll
        for (int w = 0; w < 16; w++) s += sm[w][lane];
        smf[lane] = s;
    }
    __syncthreads();

    const float n = (float)HDIM;
    float mux[4], rx[4], muh[4], rh[4];
    #pragma unroll
    for (int g = 0; g < 4; g++) {
        const float sx = smf[g * 2], sxx = smf[g * 2 + 1];
        const float sh = smf[8 + g * 2], shh = smf[8 + g * 2 + 1];
        mux[g] = sx / n;
        muh[g] = sh / n;
        const float vx = (sxx - n * mux[g] * mux[g]) / (n - 1.0f);
        const float vh = (shh - n * muh[g] * muh[g]) / (n - 1.0f);
        rx[g] = 1.0f / (sqrtf(fmaxf(vx, 0.f)) + EPS_LN);
        rh[g] = 1.0f / (sqrtf(fmaxf(vh, 0.f)) + EPS_LN);
    }

    float cv[4], og[4];
    float s = 0.f, ss = 0.f;
    #pragma unroll
    for (int i = 0; i < 4; i++) {
        const int c = tid + i * 512;
        const float axc = ax[c], bxc = bxv[c], ahc = ah[c], bhc = bhv[c];
        float G[4];
        #pragma unroll
        for (int g = 0; g < 4; g++)
            G[g] = (xv[g][i] - mux[g]) * rx[g] * axc + bxc
                 + (hv[g][i] - muh[g]) * rh[g] * ahc + bhc;
        const float fg = 1.0f / (1.0f + expf(-G[0]));
        const float ig = 1.0f / (1.0f + expf(-G[1]));
        const float v  = fg * c0[(size_t)row * HDIM + c] + ig * tanhf(G[2]);
        cv[i] = v; og[i] = G[3];
        s += v; ss += v * v;
    }

    #pragma unroll
    for (int o = 16; o > 0; o >>= 1) {
        s  += __shfl_down_sync(0xffffffffu, s, o);
        ss += __shfl_down_sync(0xffffffffu, ss, o);
    }
    __syncthreads();
    if (lane == 0) { sm[wid][0] = s; sm[wid][1] = ss; }
    __syncthreads();
    if (wid == 0 && lane < 2) {
        float t = 0.f;
        #pragma unroll
        for (int w = 0; w < 16; w++) t += sm[w][lane];
        smf[16 + lane] = t;
    }
    __syncthreads();

    const float mu = smf[16] / n;
    const float var = (smf[17] - n * mu * mu) / (n - 1.0f);
    const float rs = 1.0f / (sqrtf(fmaxf(var, 0.f)) + EPS_LN);

    __nv_bfloat16* hrow = hxcat + (size_t)row * (3 * HDIM);
    #pragma unroll
    for (int i = 0; i < 4; i++) {
        const int c = tid + i * 512;
        const float lnc = (cv[i] - mu) * rs * ac[c] + bcv[c];
        const float o = 1.0f / (1.0f + expf(-og[i]));
        const float hvv = o * tanhf(lnc);
        hx_out[(size_t)row * HDIM + c] = hvv;
        cx_out[(size_t)row * HDIM + c] = cv[i];
        const __nv_bfloat16 hi = __float2bfloat16(hvv);
        const __nv_bfloat16 lo = __float2bfloat16(hvv - __bfloat162float(hi));
        hrow[c] = hi; hrow[HDIM + c] = lo; hrow[2 * HDIM + c] = hi;
    }
}

// ---------------------------------------------------------------------------
extern "C" void kernel_launch(void* const* d_in, const int* in_sizes, int n_in,
                              void* d_out, int out_size)
{
    (void)in_sizes; (void)n_in; (void)out_size;
    const float* inp = (const float*)d_in[0];
    const float* h0  = (const float*)d_in[1];
    const float* c0  = (const float*)d_in[2];
    const float* Wfh = (const float*)d_in[3];   const float* bfh = (const float*)d_in[4];
    const float* Wih = (const float*)d_in[5];   const float* bih = (const float*)d_in[6];
    const float* Wch = (const float*)d_in[7];   const float* bch = (const float*)d_in[8];
    const float* Woh = (const float*)d_in[9];   const float* boh = (const float*)d_in[10];
    const float* Wfx = (const float*)d_in[11];  const float* bfx = (const float*)d_in[12];
    const float* Wix = (const float*)d_in[13];  const float* bix = (const float*)d_in[14];
    const float* Wcx = (const float*)d_in[15];  const float* bcx = (const float*)d_in[16];
    const float* Wox = (const float*)d_in[17];  const float* box_ = (const float*)d_in[18];
    const float* Wdec = (const float*)d_in[19]; const float* bdec = (const float*)d_in[20];
    const float* ax = (const float*)d_in[21];   const float* bx = (const float*)d_in[22];
    const float* ah = (const float*)d_in[23];   const float* bh = (const float*)d_in[24];
    const float* ac = (const float*)d_in[25];   const float* bc = (const float*)d_in[26];

    float *Xbuf, *Hbuf, *biasx, *biash;
    __nv_bfloat16 *Ax, *Ah, *Wx, *Wh, *Wd, *Hxc;
    cudaGetSymbolAddress((void**)&Xbuf, g_Xbuf);
    cudaGetSymbolAddress((void**)&Hbuf, g_Hbuf);
    cudaGetSymbolAddress((void**)&Ax, g_Ax);
    cudaGetSymbolAddress((void**)&Ah, g_Ah);
    cudaGetSymbolAddress((void**)&Wx, g_Wx);
    cudaGetSymbolAddress((void**)&Wh, g_Wh);
    cudaGetSymbolAddress((void**)&Wd, g_Wd);
    cudaGetSymbolAddress((void**)&Hxc, g_Hxc);
    cudaGetSymbolAddress((void**)&biasx, g_biasx);
    cudaGetSymbolAddress((void**)&biash, g_biash);

    cudaFuncSetAttribute(gemm_mma, cudaFuncAttributeMaxDynamicSharedMemorySize, GEMM_SMEM);

    float* out = (float*)d_out;
    float* hx  = out + (size_t)BDIM * 1024;
    float* cx  = hx + (size_t)BDIM * HDIM;

    split_kernel<<<BDIM, 256>>>(inp, Ax, 1024, 0);                         // 0
    splitW4_kernel<<<dim3(HDIM, 4), 256>>>(Wfx, Wix, Wcx, Wox, Wx, 1024);  // 1
    bias4_kernel<<<32, 256>>>(bfx, bix, bcx, box_, biasx);                 // 2
    split_kernel<<<BDIM, 256>>>(h0,  Ah, HDIM, 0);                         // 3
    splitW4_kernel<<<dim3(HDIM, 4), 256>>>(Wfh, Wih, Wch, Woh, Wh, HDIM);  // 4
    gemm_mma<<<dim3(BDIM / BM, (4 * HDIM) / BN), 256, GEMM_SMEM>>>(        // 5
        Ax, Wx, biasx, Xbuf, 3 * 1024, 4 * HDIM);
    bias4_kernel<<<32, 256>>>(bfh, bih, bch, boh, biash);                  // 6
    gemm_mma<<<dim3(BDIM / BM, (4 * HDIM) / BN), 256, GEMM_SMEM>>>(        // 7
        Ah, Wh, biash, Hbuf, 3 * HDIM, 4 * HDIM);
    split_kernel<<<1024, 256>>>(Wdec, Wd, HDIM, 1);                        // 8
    ln_cell_kernel<<<BDIM, 512>>>(Xbuf, Hbuf, c0, ax, bx, ah, bh, ac, bc,  // 9
                                  hx, cx, Hxc);
    gemm_mma<<<dim3(BDIM / BM, 1024 / BN), 256, GEMM_SMEM>>>(              // 10
        Hxc, Wd, bdec, out, 3 * HDIM, 1024);
}